// round 14
// baseline (speedup 1.0000x reference)
#include <cuda_runtime.h>
#include <cuda_fp16.h>
#include <math.h>
#include <stdint.h>

#define HIDDEN    2048
#define NUM_HEADS 16
#define HEAD_DIM  128
#define WINDOW    256
#define BATCH     2
#define SEQ       2048
#define M_ROWS    (BATCH * SEQ)        // 4096

// -------- scratch (static device buffers; no allocation allowed) --------
__device__ __half g_Qh[BATCH * NUM_HEADS * SEQ * HEAD_DIM];   // f16 post-rope, kw-scaled
__device__ __half g_Kh[BATCH * NUM_HEADS * SEQ * HEAD_DIM];   // f16 post-rope
__device__ __half g_Vh[BATCH * NUM_HEADS * SEQ * HEAD_DIM];
__device__ __half g_Xh[M_ROWS * HIDDEN];                       // x, fp16 (plain layout)
__device__ __half g_AOh[M_ROWS * HIDDEN];                      // attn out, fp16 (plain)
__device__ __half g_WTh4[4 * HIDDEN * HIDDEN];                 // W^T x4, fp16 (plain)
__device__ float2 g_rope[SEQ * 64];                            // (cos, sin) per (s, d-pair)

// ======================= helpers =======================
__device__ __forceinline__ uint32_t smem_u32(const void* p) {
    uint32_t a;
    asm("{ .reg .u64 t; cvta.to.shared.u64 t, %1; cvt.u32.u64 %0, t; }" : "=r"(a) : "l"(p));
    return a;
}
__device__ __forceinline__ void cp_async16(uint32_t saddr, const void* g) {
    asm volatile("cp.async.cg.shared.global [%0], [%1], 16;\n" :: "r"(saddr), "l"(g));
}
__device__ __forceinline__ void cp_commit() {
    asm volatile("cp.async.commit_group;\n" ::: "memory");
}
__device__ __forceinline__ void cp_wait1() {
    asm volatile("cp.async.wait_group 1;\n" ::: "memory");
}

__device__ __forceinline__ void mma_f16(
    float& c0, float& c1, float& c2, float& c3,
    uint32_t a0, uint32_t a1, uint32_t a2, uint32_t a3,
    uint32_t b0, uint32_t b1)
{
    asm volatile(
        "mma.sync.aligned.m16n8k16.row.col.f32.f16.f16.f32 "
        "{%0,%1,%2,%3},{%4,%5,%6,%7},{%8,%9},{%0,%1,%2,%3};"
        : "+f"(c0), "+f"(c1), "+f"(c2), "+f"(c3)
        : "r"(a0), "r"(a1), "r"(a2), "r"(a3), "r"(b0), "r"(b1));
}

#define LDMX4(r0, r1, r2, r3, addr) \
    asm volatile("ldmatrix.sync.aligned.m8n8.x4.shared.b16 {%0,%1,%2,%3}, [%4];" \
                 : "=r"(r0), "=r"(r1), "=r"(r2), "=r"(r3) : "r"(addr))
#define LDMX4T(r0, r1, r2, r3, addr) \
    asm volatile("ldmatrix.sync.aligned.m8n8.x4.trans.shared.b16 {%0,%1,%2,%3}, [%4];" \
                 : "=r"(r0), "=r"(r1), "=r"(r2), "=r"(r3) : "r"(addr))

__device__ __forceinline__ uint32_t packh2(float a, float b) {
    __half2 h = __floats2half2_rn(a, b);
    return *(uint32_t*)&h;
}

// ======================= FP16 tensor GEMM (round-8 proven config) =======================
#define ROWH  72                         // smem row stride in halfs (144B; 36w ≡ 4 mod 32)
#define OPSTH (128 * ROWH)               // 9216 halfs per operand per stage
#define GEMM_SMEM_BYTES (4 * OPSTH * 2)  // A[2] + B[2] = 73728 B

// inner mainloop shared by both GEMMs (acc[4][4][4] must be in scope)
#define GEMM_MAINLOOP(A_, BT_)                                                         \
    int crow[4], cseg[4];                                                              \
    _Pragma("unroll")                                                                  \
    for (int jj = 0; jj < 4; jj++) {                                                   \
        int cid = tid + jj * 256;                                                      \
        crow[jj] = cid >> 3;                                                           \
        cseg[jj] = (cid & 7) * 8;                                                      \
    }                                                                                  \
    const uint32_t sb0 = smem_u32(smh);                                                \
    const int l7 = lane & 7;                                                           \
    const uint32_t a_base = sb0 +                                                      \
        (uint32_t)(((wm * 64 + l7 + (lane & 8)) * ROWH + ((lane & 16) ? 8 : 0)) * 2);  \
    const uint32_t b_base = sb0 + 2 * OPSTH * 2 +                                      \
        (uint32_t)(((wn * 32 + (lane >> 4) * 8 + l7) * ROWH + ((lane & 8) ? 8 : 0)) * 2); \
    auto load_stage = [&](int s, int k0) {                                             \
        __half* as = smh + s * OPSTH;                                                  \
        __half* bs = smh + 2 * OPSTH + s * OPSTH;                                      \
        _Pragma("unroll")                                                              \
        for (int jj = 0; jj < 4; jj++) {                                               \
            uint32_t sa = (uint32_t)__cvta_generic_to_shared(&as[crow[jj] * ROWH + cseg[jj]]); \
            cp_async16(sa, &A_[(size_t)(m0 + crow[jj]) * HIDDEN + k0 + cseg[jj]]);     \
            uint32_t sb = (uint32_t)__cvta_generic_to_shared(&bs[crow[jj] * ROWH + cseg[jj]]); \
            cp_async16(sb, &BT_[(size_t)(n0 + crow[jj]) * HIDDEN + k0 + cseg[jj]]);    \
        }                                                                              \
        cp_commit();                                                                   \
    };                                                                                 \
    const int niter = HIDDEN / 64;                                                     \
    load_stage(0, 0);                                                                  \
    for (int it = 0; it < niter; it++) {                                               \
        const int buf = it & 1;                                                        \
        if (it + 1 < niter) load_stage(buf ^ 1, (it + 1) * 64);                        \
        else cp_commit();                                                              \
        cp_wait1();                                                                    \
        __syncthreads();                                                               \
        const uint32_t aS = a_base + (uint32_t)(buf * OPSTH * 2);                      \
        const uint32_t bS = b_base + (uint32_t)(buf * OPSTH * 2);                      \
        _Pragma("unroll")                                                              \
        for (int ks = 0; ks < 4; ks++) {                                               \
            uint32_t af[4][4], bf[2][4];                                               \
            _Pragma("unroll")                                                          \
            for (int mf = 0; mf < 4; mf++)                                             \
                LDMX4(af[mf][0], af[mf][1], af[mf][2], af[mf][3],                      \
                      aS + (uint32_t)(mf * 16 * ROWH * 2 + ks * 32));                  \
            _Pragma("unroll")                                                          \
            for (int np = 0; np < 2; np++)                                             \
                LDMX4(bf[np][0], bf[np][1], bf[np][2], bf[np][3],                      \
                      bS + (uint32_t)(np * 16 * ROWH * 2 + ks * 32));                  \
            _Pragma("unroll")                                                          \
            for (int mf = 0; mf < 4; mf++)                                             \
                _Pragma("unroll")                                                      \
                for (int np = 0; np < 2; np++) {                                       \
                    mma_f16(acc[mf][2*np][0], acc[mf][2*np][1],                        \
                            acc[mf][2*np][2], acc[mf][2*np][3],                        \
                            af[mf][0], af[mf][1], af[mf][2], af[mf][3],                \
                            bf[np][0], bf[np][1]);                                     \
                    mma_f16(acc[mf][2*np+1][0], acc[mf][2*np+1][1],                    \
                            acc[mf][2*np+1][2], acc[mf][2*np+1][3],                    \
                            af[mf][0], af[mf][1], af[mf][2], af[mf][3],                \
                            bf[np][2], bf[np][3]);                                     \
                }                                                                      \
        }                                                                              \
        __syncthreads();                                                               \
    }

// ---- fused QKV + RoPE epilogue: grid (48, 32); j = bx>>4 ----
__global__ __launch_bounds__(256, 2) void gemm_qkv(
    const __half* __restrict__ A, const __half* __restrict__ BT3,
    const float* __restrict__ bq, const float* __restrict__ bk, const float* __restrict__ bv,
    const float* __restrict__ kw,
    __half* __restrict__ Qh, __half* __restrict__ Kh, __half* __restrict__ Vh)
{
    extern __shared__ __half smh[];
    const int tid  = threadIdx.x;
    const int lane = tid & 31;
    const int warp = tid >> 5;
    const int wm   = warp >> 2;
    const int wn   = warp & 3;
    const int g    = lane >> 2;
    const int t    = lane & 3;
    const int j    = blockIdx.x >> 4;          // 0=Q 1=K 2=V
    const int h    = blockIdx.x & 15;
    const int n0   = h * 128;
    const int m0   = blockIdx.y * 128;
    const __half* BT = BT3 + (size_t)j * HIDDEN * HIDDEN;
    const float* bias = (j == 0) ? bq : (j == 1) ? bk : bv;

    float acc[4][4][4];
#pragma unroll
    for (int i = 0; i < 4; i++)
#pragma unroll
        for (int jj = 0; jj < 4; jj++)
#pragma unroll
            for (int e = 0; e < 4; e++) acc[i][jj][e] = 0.f;

    GEMM_MAINLOOP(A, BT)

    const int b = m0 >> 11;

    if (j == 2) {
        __half* Vb = Vh + (size_t)(b * NUM_HEADS + h) * SEQ * HEAD_DIM;
#pragma unroll
        for (int mf = 0; mf < 4; mf++) {
            int r0l = wm * 64 + mf * 16 + g;
            int s0 = (m0 + r0l) & (SEQ - 1);
            int s1 = s0 + 8;
#pragma unroll
            for (int nf = 0; nf < 4; nf++) {
                int col = wn * 32 + nf * 8 + 2 * t;
                float b0 = bias[n0 + col], b1 = bias[n0 + col + 1];
                *(uint32_t*)&Vb[(size_t)s0 * HEAD_DIM + col] =
                    packh2(acc[mf][nf][0] + b0, acc[mf][nf][1] + b1);
                *(uint32_t*)&Vb[(size_t)s1 * HEAD_DIM + col] =
                    packh2(acc[mf][nf][2] + b0, acc[mf][nf][3] + b1);
            }
        }
        return;
    }

    // ---- Q/K: stage through smem, apply RoPE, store fp16 ----
    float* buf = (float*)smh;   // [128][132]
#pragma unroll
    for (int mf = 0; mf < 4; mf++) {
        int r0l = wm * 64 + mf * 16 + g;
#pragma unroll
        for (int nf = 0; nf < 4; nf++) {
            int col = wn * 32 + nf * 8 + 2 * t;
            float b0 = bias[n0 + col], b1 = bias[n0 + col + 1];
            buf[r0l * 132 + col]           = acc[mf][nf][0] + b0;
            buf[r0l * 132 + col + 1]       = acc[mf][nf][1] + b1;
            buf[(r0l + 8) * 132 + col]     = acc[mf][nf][2] + b0;
            buf[(r0l + 8) * 132 + col + 1] = acc[mf][nf][3] + b1;
        }
    }
    __syncthreads();

    const float scale = (j == 0) ? kw[h] * 0.08838834764831845f : 1.0f;
    __half* dst = ((j == 0) ? Qh : Kh) + (size_t)(b * NUM_HEADS + h) * SEQ * HEAD_DIM;

#pragma unroll
    for (int it2 = 0; it2 < 8; it2++) {
        int idx = tid + it2 * 256;
        int row = idx >> 4;
        int dg  = (idx & 15) * 4;
        int s   = (m0 + row) & (SEQ - 1);
        float4 f1 = *(float4*)&buf[row * 132 + dg];
        float4 f2 = *(float4*)&buf[row * 132 + 64 + dg];
        float2 t0 = g_rope[s * 64 + dg];
        float2 t1 = g_rope[s * 64 + dg + 1];
        float2 t2 = g_rope[s * 64 + dg + 2];
        float2 t3 = g_rope[s * 64 + dg + 3];
        uint2 lo, hi;
        lo.x = packh2((f1.x * t0.x - f2.x * t0.y) * scale, (f1.y * t1.x - f2.y * t1.y) * scale);
        lo.y = packh2((f1.z * t2.x - f2.z * t2.y) * scale, (f1.w * t3.x - f2.w * t3.y) * scale);
        hi.x = packh2((f1.x * t0.y + f2.x * t0.x) * scale, (f1.y * t1.y + f2.y * t1.x) * scale);
        hi.y = packh2((f1.z * t2.y + f2.z * t2.x) * scale, (f1.w * t3.y + f2.w * t3.x) * scale);
        *(uint2*)&dst[(size_t)s * HEAD_DIM + dg]      = lo;
        *(uint2*)&dst[(size_t)s * HEAD_DIM + dg + 64] = hi;
    }
}

// ---- generic GEMM (O projection) ----
__global__ __launch_bounds__(256, 2) void gemm_f16(
    const __half* __restrict__ A, const __half* __restrict__ BT,
    const float* __restrict__ bias, float* __restrict__ C)
{
    extern __shared__ __half smh[];
    const int tid  = threadIdx.x;
    const int lane = tid & 31;
    const int warp = tid >> 5;
    const int wm   = warp >> 2;
    const int wn   = warp & 3;
    const int g    = lane >> 2;
    const int t    = lane & 3;
    const int m0   = blockIdx.y * 128;
    const int n0   = blockIdx.x * 128;

    float acc[4][4][4];
#pragma unroll
    for (int i = 0; i < 4; i++)
#pragma unroll
        for (int jj = 0; jj < 4; jj++)
#pragma unroll
            for (int e = 0; e < 4; e++) acc[i][jj][e] = 0.f;

    GEMM_MAINLOOP(A, BT)

#pragma unroll
    for (int mf = 0; mf < 4; mf++) {
        int row0 = m0 + wm * 64 + mf * 16 + g;
#pragma unroll
        for (int nf = 0; nf < 4; nf++) {
            int col = n0 + wn * 32 + nf * 8 + 2 * t;
            float b0 = bias[col], b1 = bias[col + 1];
            *(float2*)&C[(size_t)row0 * HIDDEN + col] =
                make_float2(acc[mf][nf][0] + b0, acc[mf][nf][1] + b1);
            *(float2*)&C[(size_t)(row0 + 8) * HIDDEN + col] =
                make_float2(acc[mf][nf][2] + b0, acc[mf][nf][3] + b1);
        }
    }
}

// ======================= fused prep kernel =======================
// grid (64, 64, 6), block (32, 8):
//   z in [0,4): transpose+convert weight z  ->  WT[z]
//   z == 4   : convert x -> Xh (4096 flattened blocks)
//   z == 5   : rope table (first 512 flattened blocks)
__global__ __launch_bounds__(256) void prep_kernel(
    const float* __restrict__ x,
    const float* __restrict__ W0, const float* __restrict__ W1,
    const float* __restrict__ W2, const float* __restrict__ W3,
    __half* __restrict__ Xh, __half* __restrict__ WT)
{
    const int z = blockIdx.z;
    const int tid = threadIdx.y * 32 + threadIdx.x;

    if (z < 4) {
        const float* W = (z == 0) ? W0 : (z == 1) ? W1 : (z == 2) ? W2 : W3;
        __half* dst = WT + (size_t)z * HIDDEN * HIDDEN;

        __shared__ float tle[32][33];
        int xx = blockIdx.x * 32 + threadIdx.x;
        int y0 = blockIdx.y * 32 + threadIdx.y;
#pragma unroll
        for (int i = 0; i < 4; i++)
            tle[threadIdx.y + i * 8][threadIdx.x] = W[(size_t)(y0 + i * 8) * HIDDEN + xx];
        __syncthreads();
        int xk = blockIdx.y * 32 + threadIdx.x;
        int yn = blockIdx.x * 32 + threadIdx.y;
#pragma unroll
        for (int i = 0; i < 4; i++)
            dst[(size_t)(yn + i * 8) * HIDDEN + xk] =
                __float2half_rn(tle[threadIdx.x][threadIdx.y + i * 8]);
        return;
    }

    const int bid = blockIdx.y * 64 + blockIdx.x;   // 0..4095

    if (z == 4) {
        // x -> fp16: 4096 blocks x 256 threads x 8 floats = 8388608 = M_ROWS*HIDDEN
        int i = (bid * 256 + tid) * 8;
        float4 u0 = *(const float4*)&x[i];
        float4 u1 = *(const float4*)&x[i + 4];
        __half2 h[4];
        h[0] = __floats2half2_rn(u0.x, u0.y);
        h[1] = __floats2half2_rn(u0.z, u0.w);
        h[2] = __floats2half2_rn(u1.x, u1.y);
        h[3] = __floats2half2_rn(u1.z, u1.w);
        *(uint4*)&Xh[i] = *(uint4*)&h[0];
        return;
    }

    // z == 5: rope table, 512 blocks x 256 threads = SEQ*64 entries
    if (bid < 512) {
        int idx = bid * 256 + tid;
        int s = idx >> 6, d = idx & 63;
        float inv = __expf(-(float)(2 * d) / (float)HEAD_DIM * 9.210340371976184f);
        float fr = (float)s * inv;
        float c, sn;
        sincosf(fr, &sn, &c);
        g_rope[idx] = make_float2(c, sn);
    }
}

// ======================= Tensor-core sliding-window attention =======================
#define SQH 136
#define ATTN_SMEM_BYTES ((128 + 64 + 64) * SQH * 2)   // 69632

__global__ __launch_bounds__(256, 2) void swattn_mma(
    const __half* __restrict__ Qh, const __half* __restrict__ Kh,
    const __half* __restrict__ Vh, __half* __restrict__ AOh)
{
    extern __shared__ __half smh[];
    __half* Qs = smh;                   // 128 x SQH
    __half* Ks = smh + 128 * SQH;       // 64 x SQH
    __half* Vs = smh + 192 * SQH;       // 64 x SQH

    const int tid  = threadIdx.x;
    const int w    = tid >> 5;
    const int lane = tid & 31;
    const int g    = lane >> 2;
    const int t    = lane & 3;
    const int bh   = blockIdx.y;
    const int q0   = blockIdx.x * 128;
    const int qr   = w * 16;
    const int qmin = q0 + qr;
    const int qmax = qmin + 15;

    const uint32_t qs_b = smem_u32(Qs);
    const uint32_t ks_b = smem_u32(Ks);
    const uint32_t vs_b = smem_u32(Vs);

    const int l7 = lane & 7;
    const uint32_t a_addr = qs_b +
        (uint32_t)(((qr + l7 + (lane & 8)) * SQH + ((lane & 16) ? 8 : 0)) * 2);
    const int k_rowc = ((lane >> 4) * 8 + l7);
    const int k_colo = (lane & 8) ? 8 : 0;
    const int v_rowc = (((lane >> 3) & 1) * 8 + l7);
    const int v_colc = (lane >> 4) * 8;

    const __half* Qg = Qh + (size_t)(bh * SEQ + q0) * HEAD_DIM;
#pragma unroll
    for (int it = 0; it < 8; it++) {
        int lin = tid + it * 256;
        int row = lin >> 4, seg = (lin & 15) * 8;
        *(uint4*)&Qs[row * SQH + seg] = *(const uint4*)&Qg[row * HEAD_DIM + seg];
    }

    float m0 = -1e30f, m1 = -1e30f, l0 = 0.f, l1 = 0.f;
    float oacc[16][4];
#pragma unroll
    for (int dn = 0; dn < 16; dn++)
#pragma unroll
        for (int e = 0; e < 4; e++) oacc[dn][e] = 0.f;

    const __half* Kg = Kh + (size_t)bh * SEQ * HEAD_DIM;
    const __half* Vg = Vh + (size_t)bh * SEQ * HEAD_DIM;

    int cs = q0 - WINDOW; if (cs < 0) cs = 0;
    const int kend = q0 + 64;

    for (int k0 = cs; k0 <= kend; k0 += 64) {
        __syncthreads();
#pragma unroll
        for (int it = 0; it < 4; it++) {
            int lin = tid + it * 256;
            int row = lin >> 4, seg = (lin & 15) * 8;
            *(uint4*)&Ks[row * SQH + seg] = *(const uint4*)&Kg[(size_t)(k0 + row) * HEAD_DIM + seg];
            *(uint4*)&Vs[row * SQH + seg] = *(const uint4*)&Vg[(size_t)(k0 + row) * HEAD_DIM + seg];
        }
        __syncthreads();

        const bool skip = (k0 > qmax) || (k0 + 63 < qmin - WINDOW);
        if (skip) continue;
        const bool needMask =
            (k0 + 63 >= qmin && k0 <= qmax) ||
            (k0 + 63 >= qmin - WINDOW && k0 <= qmax - WINDOW);

        float sc[8][4];
#pragma unroll
        for (int kg = 0; kg < 8; kg++)
#pragma unroll
            for (int e = 0; e < 4; e++) sc[kg][e] = 0.f;

#pragma unroll
        for (int kk = 0; kk < 8; kk++) {
            uint32_t a0, a1, a2, a3;
            LDMX4(a0, a1, a2, a3, a_addr + kk * 32);
#pragma unroll
            for (int p = 0; p < 4; p++) {
                uint32_t b0, b1, b2, b3;
                uint32_t kaddr = ks_b +
                    (uint32_t)((((k_rowc + p * 16) * SQH) + kk * 16 + k_colo) * 2);
                LDMX4(b0, b1, b2, b3, kaddr);
                mma_f16(sc[2*p][0], sc[2*p][1], sc[2*p][2], sc[2*p][3],
                        a0, a1, a2, a3, b0, b1);
                mma_f16(sc[2*p+1][0], sc[2*p+1][1], sc[2*p+1][2], sc[2*p+1][3],
                        a0, a1, a2, a3, b2, b3);
            }
        }

        if (needMask) {
            const int qga = qmin + g;
            const int qgb = qga + 8;
#pragma unroll
            for (int kg = 0; kg < 8; kg++) {
                int key = k0 + kg * 8 + 2 * t;
                if (key     > qga || key     < qga - WINDOW) sc[kg][0] = -1e30f;
                if (key + 1 > qga || key + 1 < qga - WINDOW) sc[kg][1] = -1e30f;
                if (key     > qgb || key     < qgb - WINDOW) sc[kg][2] = -1e30f;
                if (key + 1 > qgb || key + 1 < qgb - WINDOW) sc[kg][3] = -1e30f;
            }
        }

        float mx0 = -1e30f, mx1 = -1e30f;
#pragma unroll
        for (int kg = 0; kg < 8; kg++) {
            mx0 = fmaxf(mx0, fmaxf(sc[kg][0], sc[kg][1]));
            mx1 = fmaxf(mx1, fmaxf(sc[kg][2], sc[kg][3]));
        }
        mx0 = fmaxf(mx0, __shfl_xor_sync(0xffffffffu, mx0, 1));
        mx0 = fmaxf(mx0, __shfl_xor_sync(0xffffffffu, mx0, 2));
        mx1 = fmaxf(mx1, __shfl_xor_sync(0xffffffffu, mx1, 1));
        mx1 = fmaxf(mx1, __shfl_xor_sync(0xffffffffu, mx1, 2));

        float nm0 = fmaxf(m0, mx0), nm1 = fmaxf(m1, mx1);
        float rs0 = __expf(m0 - nm0), rs1 = __expf(m1 - nm1);

        float s0 = 0.f, s1 = 0.f;
        uint32_t ph[8][2];
#pragma unroll
        for (int kg = 0; kg < 8; kg++) {
            float p0 = __expf(sc[kg][0] - nm0);
            float p1 = __expf(sc[kg][1] - nm0);
            float p2 = __expf(sc[kg][2] - nm1);
            float p3 = __expf(sc[kg][3] - nm1);
            s0 += p0 + p1;
            s1 += p2 + p3;
            ph[kg][0] = packh2(p0, p1);
            ph[kg][1] = packh2(p2, p3);
        }
        s0 += __shfl_xor_sync(0xffffffffu, s0, 1);
        s0 += __shfl_xor_sync(0xffffffffu, s0, 2);
        s1 += __shfl_xor_sync(0xffffffffu, s1, 1);
        s1 += __shfl_xor_sync(0xffffffffu, s1, 2);

        l0 = l0 * rs0 + s0;
        l1 = l1 * rs1 + s1;
        m0 = nm0; m1 = nm1;

#pragma unroll
        for (int dn = 0; dn < 16; dn++) {
            oacc[dn][0] *= rs0; oacc[dn][1] *= rs0;
            oacc[dn][2] *= rs1; oacc[dn][3] *= rs1;
        }

#pragma unroll
        for (int ck = 0; ck < 4; ck++) {
            uint32_t pa0 = ph[2*ck][0], pa1 = ph[2*ck][1];
            uint32_t pa2 = ph[2*ck+1][0], pa3 = ph[2*ck+1][1];
#pragma unroll
            for (int dp = 0; dp < 8; dp++) {
                uint32_t v0, v1, v2, v3;
                uint32_t vaddr = vs_b +
                    (uint32_t)((((v_rowc + ck * 16) * SQH) + dp * 16 + v_colc) * 2);
                LDMX4T(v0, v1, v2, v3, vaddr);
                mma_f16(oacc[2*dp][0], oacc[2*dp][1], oacc[2*dp][2], oacc[2*dp][3],
                        pa0, pa1, pa2, pa3, v0, v1);
                mma_f16(oacc[2*dp+1][0], oacc[2*dp+1][1], oacc[2*dp+1][2], oacc[2*dp+1][3],
                        pa0, pa1, pa2, pa3, v2, v3);
            }
        }
    }

    // ---- epilogue: normalize + fp16 plain-layout store ----
    float inv0 = 1.f / l0, inv1 = 1.f / l1;
    const int b = bh >> 4, h = bh & (NUM_HEADS - 1);
    size_t rowa = (size_t)(b * SEQ + q0 + qr + g) * HIDDEN;
    size_t rowb = rowa + (size_t)8 * HIDDEN;
#pragma unroll
    for (int dn = 0; dn < 16; dn++) {
        int a = dn & 1;
        int col = h * 128 + (dn >> 1) * 16 + a * 8 + 2 * t;
        *(uint32_t*)&AOh[rowa + col] = packh2(oacc[dn][0] * inv0, oacc[dn][1] * inv0);
        *(uint32_t*)&AOh[rowb + col] = packh2(oacc[dn][2] * inv1, oacc[dn][3] * inv1);
    }
}

// ======================= launch =======================
extern "C" void kernel_launch(void* const* d_in, const int* in_sizes, int n_in,
                              void* d_out, int out_size)
{
    const float* x   = (const float*)d_in[0];
    const float* W_Q = (const float*)d_in[1];
    const float* b_Q = (const float*)d_in[2];
    const float* W_K = (const float*)d_in[3];
    const float* b_K = (const float*)d_in[4];
    const float* W_V = (const float*)d_in[5];
    const float* b_V = (const float*)d_in[6];
    const float* W_O = (const float*)d_in[7];
    const float* b_O = (const float*)d_in[8];
    const float* kw  = (const float*)d_in[9];

    __half *Qh, *Kh, *Vh, *Xh, *AOh, *WTh4;
    cudaGetSymbolAddress((void**)&Qh,   g_Qh);
    cudaGetSymbolAddress((void**)&Kh,   g_Kh);
    cudaGetSymbolAddress((void**)&Vh,   g_Vh);
    cudaGetSymbolAddress((void**)&Xh,   g_Xh);
    cudaGetSymbolAddress((void**)&AOh,  g_AOh);
    cudaGetSymbolAddress((void**)&WTh4, g_WTh4);

    cudaFuncSetAttribute(gemm_qkv,
                         cudaFuncAttributeMaxDynamicSharedMemorySize, GEMM_SMEM_BYTES);
    cudaFuncSetAttribute(gemm_f16,
                         cudaFuncAttributeMaxDynamicSharedMemorySize, GEMM_SMEM_BYTES);
    cudaFuncSetAttribute(swattn_mma,
                         cudaFuncAttributeMaxDynamicSharedMemorySize, ATTN_SMEM_BYTES);

    // 0. ALL prep in one launch: 4 weight transposes + x conversion + rope table
    dim3 pg(HIDDEN / 32, HIDDEN / 32, 6);
    dim3 pb(32, 8);
    prep_kernel<<<pg, pb>>>(x, W_Q, W_K, W_V, W_O, Xh, WTh4);

    // 1. fused QKV GEMM + RoPE epilogue
    dim3 gq(48, M_ROWS / 128);
    gemm_qkv<<<gq, 256, GEMM_SMEM_BYTES>>>(Xh, WTh4, b_Q, b_K, b_V, kw, Qh, Kh, Vh);

    // 2. attention (128-query tiles, 2 CTAs/SM)
    dim3 ga(SEQ / 128, BATCH * NUM_HEADS);
    swattn_mma<<<ga, 256, ATTN_SMEM_BYTES>>>(Qh, Kh, Vh, AOh);

    // 3. O projection
    dim3 go(HIDDEN / 128, M_ROWS / 128);
    gemm_f16<<<go, 256, GEMM_SMEM_BYTES>>>(AOh, WTh4 + (size_t)3 * HIDDEN * HIDDEN,
                                           b_O, (float*)d_out);
}

// round 15
// speedup vs baseline: 1.5095x; 1.5095x over previous
#include <cuda_runtime.h>
#include <cuda_fp16.h>
#include <math.h>
#include <stdint.h>

#define HIDDEN    2048
#define NUM_HEADS 16
#define HEAD_DIM  128
#define WINDOW    256
#define BATCH     2
#define SEQ       2048
#define M_ROWS    (BATCH * SEQ)        // 4096

// -------- scratch (static device buffers; no allocation allowed) --------
__device__ __half g_Qh[BATCH * NUM_HEADS * SEQ * HEAD_DIM];   // f16 post-rope, kw-scaled
__device__ __half g_Kh[BATCH * NUM_HEADS * SEQ * HEAD_DIM];   // f16 post-rope
__device__ __half g_Vh[BATCH * NUM_HEADS * SEQ * HEAD_DIM];
__device__ __half g_Xh[M_ROWS * HIDDEN];                       // x, fp16 (plain layout)
__device__ __half g_AOh[M_ROWS * HIDDEN];                      // attn out, fp16 (plain)
__device__ __half g_WTh4[4 * HIDDEN * HIDDEN];                 // W^T x4, fp16 (plain)
__device__ float2 g_rope[SEQ * 64];                            // (cos, sin) per (s, d-pair)

// ======================= helpers =======================
__device__ __forceinline__ uint32_t smem_u32(const void* p) {
    uint32_t a;
    asm("{ .reg .u64 t; cvta.to.shared.u64 t, %1; cvt.u32.u64 %0, t; }" : "=r"(a) : "l"(p));
    return a;
}
__device__ __forceinline__ void cp_async16(uint32_t saddr, const void* g) {
    asm volatile("cp.async.cg.shared.global [%0], [%1], 16;\n" :: "r"(saddr), "l"(g));
}
__device__ __forceinline__ void cp_commit() {
    asm volatile("cp.async.commit_group;\n" ::: "memory");
}
__device__ __forceinline__ void cp_wait1() {
    asm volatile("cp.async.wait_group 1;\n" ::: "memory");
}

__device__ __forceinline__ void mma_f16(
    float& c0, float& c1, float& c2, float& c3,
    uint32_t a0, uint32_t a1, uint32_t a2, uint32_t a3,
    uint32_t b0, uint32_t b1)
{
    asm volatile(
        "mma.sync.aligned.m16n8k16.row.col.f32.f16.f16.f32 "
        "{%0,%1,%2,%3},{%4,%5,%6,%7},{%8,%9},{%0,%1,%2,%3};"
        : "+f"(c0), "+f"(c1), "+f"(c2), "+f"(c3)
        : "r"(a0), "r"(a1), "r"(a2), "r"(a3), "r"(b0), "r"(b1));
}

#define LDMX4(r0, r1, r2, r3, addr) \
    asm volatile("ldmatrix.sync.aligned.m8n8.x4.shared.b16 {%0,%1,%2,%3}, [%4];" \
                 : "=r"(r0), "=r"(r1), "=r"(r2), "=r"(r3) : "r"(addr))
#define LDMX4T(r0, r1, r2, r3, addr) \
    asm volatile("ldmatrix.sync.aligned.m8n8.x4.trans.shared.b16 {%0,%1,%2,%3}, [%4];" \
                 : "=r"(r0), "=r"(r1), "=r"(r2), "=r"(r3) : "r"(addr))

__device__ __forceinline__ uint32_t packh2(float a, float b) {
    __half2 h = __floats2half2_rn(a, b);
    return *(uint32_t*)&h;
}

// ======================= rope table =======================
__global__ __launch_bounds__(256) void rope_table_kernel()
{
    int idx = blockIdx.x * 256 + threadIdx.x;     // SEQ*64
    int s = idx >> 6, d = idx & 63;
    float inv = __expf(-(float)(2 * d) / (float)HEAD_DIM * 9.210340371976184f); // ln(1e4)
    float fr = (float)s * inv;
    float c, sn;
    sincosf(fr, &sn, &c);
    g_rope[idx] = make_float2(c, sn);
}

// ======================= FP16 tensor GEMM (round-8 proven config) =======================
#define ROWH  72                         // smem row stride in halfs (144B; 36w ≡ 4 mod 32)
#define OPSTH (128 * ROWH)               // 9216 halfs per operand per stage
#define GEMM_SMEM_BYTES (4 * OPSTH * 2)  // A[2] + B[2] = 73728 B

// inner mainloop shared by both GEMMs (acc[4][4][4] must be in scope)
#define GEMM_MAINLOOP(A_, BT_)                                                         \
    int crow[4], cseg[4];                                                              \
    _Pragma("unroll")                                                                  \
    for (int jj = 0; jj < 4; jj++) {                                                   \
        int cid = tid + jj * 256;                                                      \
        crow[jj] = cid >> 3;                                                           \
        cseg[jj] = (cid & 7) * 8;                                                      \
    }                                                                                  \
    const uint32_t sb0 = smem_u32(smh);                                                \
    const int l7 = lane & 7;                                                           \
    const uint32_t a_base = sb0 +                                                      \
        (uint32_t)(((wm * 64 + l7 + (lane & 8)) * ROWH + ((lane & 16) ? 8 : 0)) * 2);  \
    const uint32_t b_base = sb0 + 2 * OPSTH * 2 +                                      \
        (uint32_t)(((wn * 32 + (lane >> 4) * 8 + l7) * ROWH + ((lane & 8) ? 8 : 0)) * 2); \
    auto load_stage = [&](int s, int k0) {                                             \
        __half* as = smh + s * OPSTH;                                                  \
        __half* bs = smh + 2 * OPSTH + s * OPSTH;                                      \
        _Pragma("unroll")                                                              \
        for (int jj = 0; jj < 4; jj++) {                                               \
            uint32_t sa = (uint32_t)__cvta_generic_to_shared(&as[crow[jj] * ROWH + cseg[jj]]); \
            cp_async16(sa, &A_[(size_t)(m0 + crow[jj]) * HIDDEN + k0 + cseg[jj]]);     \
            uint32_t sb = (uint32_t)__cvta_generic_to_shared(&bs[crow[jj] * ROWH + cseg[jj]]); \
            cp_async16(sb, &BT_[(size_t)(n0 + crow[jj]) * HIDDEN + k0 + cseg[jj]]);    \
        }                                                                              \
        cp_commit();                                                                   \
    };                                                                                 \
    const int niter = HIDDEN / 64;                                                     \
    load_stage(0, 0);                                                                  \
    for (int it = 0; it < niter; it++) {                                               \
        const int buf = it & 1;                                                        \
        if (it + 1 < niter) load_stage(buf ^ 1, (it + 1) * 64);                        \
        else cp_commit();                                                              \
        cp_wait1();                                                                    \
        __syncthreads();                                                               \
        const uint32_t aS = a_base + (uint32_t)(buf * OPSTH * 2);                      \
        const uint32_t bS = b_base + (uint32_t)(buf * OPSTH * 2);                      \
        _Pragma("unroll")                                                              \
        for (int ks = 0; ks < 4; ks++) {                                               \
            uint32_t af[4][4], bf[2][4];                                               \
            _Pragma("unroll")                                                          \
            for (int mf = 0; mf < 4; mf++)                                             \
                LDMX4(af[mf][0], af[mf][1], af[mf][2], af[mf][3],                      \
                      aS + (uint32_t)(mf * 16 * ROWH * 2 + ks * 32));                  \
            _Pragma("unroll")                                                          \
            for (int np = 0; np < 2; np++)                                             \
                LDMX4(bf[np][0], bf[np][1], bf[np][2], bf[np][3],                      \
                      bS + (uint32_t)(np * 16 * ROWH * 2 + ks * 32));                  \
            _Pragma("unroll")                                                          \
            for (int mf = 0; mf < 4; mf++)                                             \
                _Pragma("unroll")                                                      \
                for (int np = 0; np < 2; np++) {                                       \
                    mma_f16(acc[mf][2*np][0], acc[mf][2*np][1],                        \
                            acc[mf][2*np][2], acc[mf][2*np][3],                        \
                            af[mf][0], af[mf][1], af[mf][2], af[mf][3],                \
                            bf[np][0], bf[np][1]);                                     \
                    mma_f16(acc[mf][2*np+1][0], acc[mf][2*np+1][1],                    \
                            acc[mf][2*np+1][2], acc[mf][2*np+1][3],                    \
                            af[mf][0], af[mf][1], af[mf][2], af[mf][3],                \
                            bf[np][2], bf[np][3]);                                     \
                }                                                                      \
        }                                                                              \
        __syncthreads();                                                               \
    }

// ---- fused QKV + RoPE epilogue: grid (48, 32); j = bx>>4 ----
__global__ __launch_bounds__(256, 2) void gemm_qkv(
    const __half* __restrict__ A, const __half* __restrict__ BT3,
    const float* __restrict__ bq, const float* __restrict__ bk, const float* __restrict__ bv,
    const float* __restrict__ kw,
    __half* __restrict__ Qh, __half* __restrict__ Kh, __half* __restrict__ Vh)
{
    extern __shared__ __half smh[];
    const int tid  = threadIdx.x;
    const int lane = tid & 31;
    const int warp = tid >> 5;
    const int wm   = warp >> 2;
    const int wn   = warp & 3;
    const int g    = lane >> 2;
    const int t    = lane & 3;
    const int j    = blockIdx.x >> 4;          // 0=Q 1=K 2=V
    const int h    = blockIdx.x & 15;
    const int n0   = h * 128;
    const int m0   = blockIdx.y * 128;
    const __half* BT = BT3 + (size_t)j * HIDDEN * HIDDEN;
    const float* bias = (j == 0) ? bq : (j == 1) ? bk : bv;

    float acc[4][4][4];
#pragma unroll
    for (int i = 0; i < 4; i++)
#pragma unroll
        for (int jj = 0; jj < 4; jj++)
#pragma unroll
            for (int e = 0; e < 4; e++) acc[i][jj][e] = 0.f;

    GEMM_MAINLOOP(A, BT)

    const int b = m0 >> 11;

    if (j == 2) {
        __half* Vb = Vh + (size_t)(b * NUM_HEADS + h) * SEQ * HEAD_DIM;
#pragma unroll
        for (int mf = 0; mf < 4; mf++) {
            int r0l = wm * 64 + mf * 16 + g;
            int s0 = (m0 + r0l) & (SEQ - 1);
            int s1 = s0 + 8;
#pragma unroll
            for (int nf = 0; nf < 4; nf++) {
                int col = wn * 32 + nf * 8 + 2 * t;
                float b0 = bias[n0 + col], b1 = bias[n0 + col + 1];
                *(uint32_t*)&Vb[(size_t)s0 * HEAD_DIM + col] =
                    packh2(acc[mf][nf][0] + b0, acc[mf][nf][1] + b1);
                *(uint32_t*)&Vb[(size_t)s1 * HEAD_DIM + col] =
                    packh2(acc[mf][nf][2] + b0, acc[mf][nf][3] + b1);
            }
        }
        return;
    }

    // ---- Q/K: stage through smem, apply RoPE, store fp16 ----
    float* buf = (float*)smh;   // [128][132]
#pragma unroll
    for (int mf = 0; mf < 4; mf++) {
        int r0l = wm * 64 + mf * 16 + g;
#pragma unroll
        for (int nf = 0; nf < 4; nf++) {
            int col = wn * 32 + nf * 8 + 2 * t;
            float b0 = bias[n0 + col], b1 = bias[n0 + col + 1];
            buf[r0l * 132 + col]           = acc[mf][nf][0] + b0;
            buf[r0l * 132 + col + 1]       = acc[mf][nf][1] + b1;
            buf[(r0l + 8) * 132 + col]     = acc[mf][nf][2] + b0;
            buf[(r0l + 8) * 132 + col + 1] = acc[mf][nf][3] + b1;
        }
    }
    __syncthreads();

    const float scale = (j == 0) ? kw[h] * 0.08838834764831845f : 1.0f;
    __half* dst = ((j == 0) ? Qh : Kh) + (size_t)(b * NUM_HEADS + h) * SEQ * HEAD_DIM;

#pragma unroll
    for (int it2 = 0; it2 < 8; it2++) {
        int idx = tid + it2 * 256;
        int row = idx >> 4;
        int dg  = (idx & 15) * 4;
        int s   = (m0 + row) & (SEQ - 1);
        float4 f1 = *(float4*)&buf[row * 132 + dg];
        float4 f2 = *(float4*)&buf[row * 132 + 64 + dg];
        float2 t0 = g_rope[s * 64 + dg];
        float2 t1 = g_rope[s * 64 + dg + 1];
        float2 t2 = g_rope[s * 64 + dg + 2];
        float2 t3 = g_rope[s * 64 + dg + 3];
        uint2 lo, hi;
        lo.x = packh2((f1.x * t0.x - f2.x * t0.y) * scale, (f1.y * t1.x - f2.y * t1.y) * scale);
        lo.y = packh2((f1.z * t2.x - f2.z * t2.y) * scale, (f1.w * t3.x - f2.w * t3.y) * scale);
        hi.x = packh2((f1.x * t0.y + f2.x * t0.x) * scale, (f1.y * t1.y + f2.y * t1.x) * scale);
        hi.y = packh2((f1.z * t2.y + f2.z * t2.x) * scale, (f1.w * t3.y + f2.w * t3.x) * scale);
        *(uint2*)&dst[(size_t)s * HEAD_DIM + dg]      = lo;
        *(uint2*)&dst[(size_t)s * HEAD_DIM + dg + 64] = hi;
    }
}

// ---- generic GEMM (O projection) ----
__global__ __launch_bounds__(256, 2) void gemm_f16(
    const __half* __restrict__ A, const __half* __restrict__ BT,
    const float* __restrict__ bias, float* __restrict__ C)
{
    extern __shared__ __half smh[];
    const int tid  = threadIdx.x;
    const int lane = tid & 31;
    const int warp = tid >> 5;
    const int wm   = warp >> 2;
    const int wn   = warp & 3;
    const int g    = lane >> 2;
    const int t    = lane & 3;
    const int m0   = blockIdx.y * 128;
    const int n0   = blockIdx.x * 128;

    float acc[4][4][4];
#pragma unroll
    for (int i = 0; i < 4; i++)
#pragma unroll
        for (int jj = 0; jj < 4; jj++)
#pragma unroll
            for (int e = 0; e < 4; e++) acc[i][jj][e] = 0.f;

    GEMM_MAINLOOP(A, BT)

#pragma unroll
    for (int mf = 0; mf < 4; mf++) {
        int row0 = m0 + wm * 64 + mf * 16 + g;
#pragma unroll
        for (int nf = 0; nf < 4; nf++) {
            int col = n0 + wn * 32 + nf * 8 + 2 * t;
            float b0 = bias[col], b1 = bias[col + 1];
            *(float2*)&C[(size_t)row0 * HIDDEN + col] =
                make_float2(acc[mf][nf][0] + b0, acc[mf][nf][1] + b1);
            *(float2*)&C[(size_t)(row0 + 8) * HIDDEN + col] =
                make_float2(acc[mf][nf][2] + b0, acc[mf][nf][3] + b1);
        }
    }
}

// ======================= prep kernels =======================
__global__ __launch_bounds__(256) void convert_half_kernel(
    const float* __restrict__ in, __half* __restrict__ out)
{
    int i = (blockIdx.x * 256 + threadIdx.x) * 8;
    float4 u0 = *(const float4*)&in[i];
    float4 u1 = *(const float4*)&in[i + 4];
    __half2 h[4];
    h[0] = __floats2half2_rn(u0.x, u0.y);
    h[1] = __floats2half2_rn(u0.z, u0.w);
    h[2] = __floats2half2_rn(u1.x, u1.y);
    h[3] = __floats2half2_rn(u1.z, u1.w);
    *(uint4*)&out[i] = *(uint4*)&h[0];
}

__global__ __launch_bounds__(256) void transpose_convert4_kernel(
    const float* __restrict__ W0, const float* __restrict__ W1,
    const float* __restrict__ W2, const float* __restrict__ W3,
    __half* __restrict__ WT)
{
    const int z = blockIdx.z;
    const float* W = (z == 0) ? W0 : (z == 1) ? W1 : (z == 2) ? W2 : W3;
    __half* dst = WT + (size_t)z * HIDDEN * HIDDEN;

    __shared__ float tle[32][33];
    int x  = blockIdx.x * 32 + threadIdx.x;
    int y0 = blockIdx.y * 32 + threadIdx.y;
#pragma unroll
    for (int i = 0; i < 4; i++)
        tle[threadIdx.y + i * 8][threadIdx.x] = W[(size_t)(y0 + i * 8) * HIDDEN + x];
    __syncthreads();
    int xk = blockIdx.y * 32 + threadIdx.x;
    int yn = blockIdx.x * 32 + threadIdx.y;
#pragma unroll
    for (int i = 0; i < 4; i++)
        dst[(size_t)(yn + i * 8) * HIDDEN + xk] =
            __float2half_rn(tle[threadIdx.x][threadIdx.y + i * 8]);
}

// ======================= Tensor-core sliding-window attention =======================
#define SQH 136
#define ATTN_SMEM_BYTES ((128 + 64 + 64) * SQH * 2)   // 69632

__global__ __launch_bounds__(256, 2) void swattn_mma(
    const __half* __restrict__ Qh, const __half* __restrict__ Kh,
    const __half* __restrict__ Vh, __half* __restrict__ AOh)
{
    extern __shared__ __half smh[];
    __half* Qs = smh;                   // 128 x SQH
    __half* Ks = smh + 128 * SQH;       // 64 x SQH
    __half* Vs = smh + 192 * SQH;       // 64 x SQH

    const int tid  = threadIdx.x;
    const int w    = tid >> 5;
    const int lane = tid & 31;
    const int g    = lane >> 2;
    const int t    = lane & 3;
    const int bh   = blockIdx.y;
    const int q0   = blockIdx.x * 128;
    const int qr   = w * 16;
    const int qmin = q0 + qr;
    const int qmax = qmin + 15;

    const uint32_t qs_b = smem_u32(Qs);
    const uint32_t ks_b = smem_u32(Ks);
    const uint32_t vs_b = smem_u32(Vs);

    const int l7 = lane & 7;
    const uint32_t a_addr = qs_b +
        (uint32_t)(((qr + l7 + (lane & 8)) * SQH + ((lane & 16) ? 8 : 0)) * 2);
    const int k_rowc = ((lane >> 4) * 8 + l7);
    const int k_colo = (lane & 8) ? 8 : 0;
    const int v_rowc = (((lane >> 3) & 1) * 8 + l7);
    const int v_colc = (lane >> 4) * 8;

    const __half* Qg = Qh + (size_t)(bh * SEQ + q0) * HEAD_DIM;
#pragma unroll
    for (int it = 0; it < 8; it++) {
        int lin = tid + it * 256;
        int row = lin >> 4, seg = (lin & 15) * 8;
        *(uint4*)&Qs[row * SQH + seg] = *(const uint4*)&Qg[row * HEAD_DIM + seg];
    }

    float m0 = -1e30f, m1 = -1e30f, l0 = 0.f, l1 = 0.f;
    float oacc[16][4];
#pragma unroll
    for (int dn = 0; dn < 16; dn++)
#pragma unroll
        for (int e = 0; e < 4; e++) oacc[dn][e] = 0.f;

    const __half* Kg = Kh + (size_t)bh * SEQ * HEAD_DIM;
    const __half* Vg = Vh + (size_t)bh * SEQ * HEAD_DIM;

    int cs = q0 - WINDOW; if (cs < 0) cs = 0;
    const int kend = q0 + 64;

    for (int k0 = cs; k0 <= kend; k0 += 64) {
        __syncthreads();
#pragma unroll
        for (int it = 0; it < 4; it++) {
            int lin = tid + it * 256;
            int row = lin >> 4, seg = (lin & 15) * 8;
            *(uint4*)&Ks[row * SQH + seg] = *(const uint4*)&Kg[(size_t)(k0 + row) * HEAD_DIM + seg];
            *(uint4*)&Vs[row * SQH + seg] = *(const uint4*)&Vg[(size_t)(k0 + row) * HEAD_DIM + seg];
        }
        __syncthreads();

        const bool skip = (k0 > qmax) || (k0 + 63 < qmin - WINDOW);
        if (skip) continue;
        const bool needMask =
            (k0 + 63 >= qmin && k0 <= qmax) ||
            (k0 + 63 >= qmin - WINDOW && k0 <= qmax - WINDOW);

        float sc[8][4];
#pragma unroll
        for (int kg = 0; kg < 8; kg++)
#pragma unroll
            for (int e = 0; e < 4; e++) sc[kg][e] = 0.f;

#pragma unroll
        for (int kk = 0; kk < 8; kk++) {
            uint32_t a0, a1, a2, a3;
            LDMX4(a0, a1, a2, a3, a_addr + kk * 32);
#pragma unroll
            for (int p = 0; p < 4; p++) {
                uint32_t b0, b1, b2, b3;
                uint32_t kaddr = ks_b +
                    (uint32_t)((((k_rowc + p * 16) * SQH) + kk * 16 + k_colo) * 2);
                LDMX4(b0, b1, b2, b3, kaddr);
                mma_f16(sc[2*p][0], sc[2*p][1], sc[2*p][2], sc[2*p][3],
                        a0, a1, a2, a3, b0, b1);
                mma_f16(sc[2*p+1][0], sc[2*p+1][1], sc[2*p+1][2], sc[2*p+1][3],
                        a0, a1, a2, a3, b2, b3);
            }
        }

        if (needMask) {
            const int qga = qmin + g;
            const int qgb = qga + 8;
#pragma unroll
            for (int kg = 0; kg < 8; kg++) {
                int key = k0 + kg * 8 + 2 * t;
                if (key     > qga || key     < qga - WINDOW) sc[kg][0] = -1e30f;
                if (key + 1 > qga || key + 1 < qga - WINDOW) sc[kg][1] = -1e30f;
                if (key     > qgb || key     < qgb - WINDOW) sc[kg][2] = -1e30f;
                if (key + 1 > qgb || key + 1 < qgb - WINDOW) sc[kg][3] = -1e30f;
            }
        }

        float mx0 = -1e30f, mx1 = -1e30f;
#pragma unroll
        for (int kg = 0; kg < 8; kg++) {
            mx0 = fmaxf(mx0, fmaxf(sc[kg][0], sc[kg][1]));
            mx1 = fmaxf(mx1, fmaxf(sc[kg][2], sc[kg][3]));
        }
        mx0 = fmaxf(mx0, __shfl_xor_sync(0xffffffffu, mx0, 1));
        mx0 = fmaxf(mx0, __shfl_xor_sync(0xffffffffu, mx0, 2));
        mx1 = fmaxf(mx1, __shfl_xor_sync(0xffffffffu, mx1, 1));
        mx1 = fmaxf(mx1, __shfl_xor_sync(0xffffffffu, mx1, 2));

        float nm0 = fmaxf(m0, mx0), nm1 = fmaxf(m1, mx1);
        float rs0 = __expf(m0 - nm0), rs1 = __expf(m1 - nm1);

        float s0 = 0.f, s1 = 0.f;
        uint32_t ph[8][2];
#pragma unroll
        for (int kg = 0; kg < 8; kg++) {
            float p0 = __expf(sc[kg][0] - nm0);
            float p1 = __expf(sc[kg][1] - nm0);
            float p2 = __expf(sc[kg][2] - nm1);
            float p3 = __expf(sc[kg][3] - nm1);
            s0 += p0 + p1;
            s1 += p2 + p3;
            ph[kg][0] = packh2(p0, p1);
            ph[kg][1] = packh2(p2, p3);
        }
        s0 += __shfl_xor_sync(0xffffffffu, s0, 1);
        s0 += __shfl_xor_sync(0xffffffffu, s0, 2);
        s1 += __shfl_xor_sync(0xffffffffu, s1, 1);
        s1 += __shfl_xor_sync(0xffffffffu, s1, 2);

        l0 = l0 * rs0 + s0;
        l1 = l1 * rs1 + s1;
        m0 = nm0; m1 = nm1;

#pragma unroll
        for (int dn = 0; dn < 16; dn++) {
            oacc[dn][0] *= rs0; oacc[dn][1] *= rs0;
            oacc[dn][2] *= rs1; oacc[dn][3] *= rs1;
        }

#pragma unroll
        for (int ck = 0; ck < 4; ck++) {
            uint32_t pa0 = ph[2*ck][0], pa1 = ph[2*ck][1];
            uint32_t pa2 = ph[2*ck+1][0], pa3 = ph[2*ck+1][1];
#pragma unroll
            for (int dp = 0; dp < 8; dp++) {
                uint32_t v0, v1, v2, v3;
                uint32_t vaddr = vs_b +
                    (uint32_t)((((v_rowc + ck * 16) * SQH) + dp * 16 + v_colc) * 2);
                LDMX4T(v0, v1, v2, v3, vaddr);
                mma_f16(oacc[2*dp][0], oacc[2*dp][1], oacc[2*dp][2], oacc[2*dp][3],
                        pa0, pa1, pa2, pa3, v0, v1);
                mma_f16(oacc[2*dp+1][0], oacc[2*dp+1][1], oacc[2*dp+1][2], oacc[2*dp+1][3],
                        pa0, pa1, pa2, pa3, v2, v3);
            }
        }
    }

    // ---- epilogue: normalize + fp16 plain-layout store ----
    float inv0 = 1.f / l0, inv1 = 1.f / l1;
    const int b = bh >> 4, h = bh & (NUM_HEADS - 1);
    size_t rowa = (size_t)(b * SEQ + q0 + qr + g) * HIDDEN;
    size_t rowb = rowa + (size_t)8 * HIDDEN;
#pragma unroll
    for (int dn = 0; dn < 16; dn++) {
        int a = dn & 1;
        int col = h * 128 + (dn >> 1) * 16 + a * 8 + 2 * t;
        *(uint32_t*)&AOh[rowa + col] = packh2(oacc[dn][0] * inv0, oacc[dn][1] * inv0);
        *(uint32_t*)&AOh[rowb + col] = packh2(oacc[dn][2] * inv1, oacc[dn][3] * inv1);
    }
}

// ======================= launch =======================
extern "C" void kernel_launch(void* const* d_in, const int* in_sizes, int n_in,
                              void* d_out, int out_size)
{
    const float* x   = (const float*)d_in[0];
    const float* W_Q = (const float*)d_in[1];
    const float* b_Q = (const float*)d_in[2];
    const float* W_K = (const float*)d_in[3];
    const float* b_K = (const float*)d_in[4];
    const float* W_V = (const float*)d_in[5];
    const float* b_V = (const float*)d_in[6];
    const float* W_O = (const float*)d_in[7];
    const float* b_O = (const float*)d_in[8];
    const float* kw  = (const float*)d_in[9];

    __half *Qh, *Kh, *Vh, *Xh, *AOh, *WTh4;
    cudaGetSymbolAddress((void**)&Qh,   g_Qh);
    cudaGetSymbolAddress((void**)&Kh,   g_Kh);
    cudaGetSymbolAddress((void**)&Vh,   g_Vh);
    cudaGetSymbolAddress((void**)&Xh,   g_Xh);
    cudaGetSymbolAddress((void**)&AOh,  g_AOh);
    cudaGetSymbolAddress((void**)&WTh4, g_WTh4);

    cudaFuncSetAttribute(gemm_qkv,
                         cudaFuncAttributeMaxDynamicSharedMemorySize, GEMM_SMEM_BYTES);
    cudaFuncSetAttribute(gemm_f16,
                         cudaFuncAttributeMaxDynamicSharedMemorySize, GEMM_SMEM_BYTES);
    cudaFuncSetAttribute(swattn_mma,
                         cudaFuncAttributeMaxDynamicSharedMemorySize, ATTN_SMEM_BYTES);

    // 0. rope table + input conversion
    rope_table_kernel<<<SEQ * 64 / 256, 256>>>();
    convert_half_kernel<<<M_ROWS * HIDDEN / (256 * 8), 256>>>(x, Xh);

    // 1. all 4 weight transposes, one launch
    dim3 tg(HIDDEN / 32, HIDDEN / 32, 4);
    dim3 tb(32, 8);
    transpose_convert4_kernel<<<tg, tb>>>(W_Q, W_K, W_V, W_O, WTh4);

    // 2. fused QKV GEMM + RoPE epilogue
    dim3 gq(48, M_ROWS / 128);
    gemm_qkv<<<gq, 256, GEMM_SMEM_BYTES>>>(Xh, WTh4, b_Q, b_K, b_V, kw, Qh, Kh, Vh);

    // 3. attention (128-query tiles, 2 CTAs/SM)
    dim3 ga(SEQ / 128, BATCH * NUM_HEADS);
    swattn_mma<<<ga, 256, ATTN_SMEM_BYTES>>>(Qh, Kh, Vh, AOh);

    // 4. O projection
    dim3 go(HIDDEN / 128, M_ROWS / 128);
    gemm_f16<<<go, 256, GEMM_SMEM_BYTES>>>(AOh, WTh4 + (size_t)3 * HIDDEN * HIDDEN,
                                           b_O, (float*)d_out);
}